// round 5
// baseline (speedup 1.0000x reference)
#include <cuda_runtime.h>
#include <cuda_bf16.h>

// Embedding gather: out[row, :] = w[x[row], :]
// x: [16384] int32, w: [50257, 1024] fp32, out: [16384, 1024] fp32
//
// 8 rows per block, 256 threads. Each thread owns one float4 column slot and
// front-batches 8 independent gather LDG.128s (MLP=8) before storing.
// Plain STG.128 (no .cs) — let L2 absorb the write stream and write back lazily.

#define EMB_DIM 1024
#define VEC_PER_ROW (EMB_DIM / 4)   // 256 float4 per row
#define ROWS_PER_BLOCK 8

__global__ void __launch_bounds__(256) embedding_gather_kernel(
    const int* __restrict__ x,
    const float4* __restrict__ w,
    float4* __restrict__ out,
    int n_rows)
{
    int row0 = blockIdx.x * ROWS_PER_BLOCK;
    int c = threadIdx.x;                       // column slot 0..255

    // Uniform index loads: 8 ints as two int4 (x is 32B-aligned at row0%8==0)
    int4 ia = __ldg((const int4*)(x + row0));
    int4 ib = __ldg((const int4*)(x + row0 + 4));

    const float4* base = w + c;

    // Front-batched independent gathers: MLP = 8
    float4 v0 = __ldg(base + (size_t)ia.x * VEC_PER_ROW);
    float4 v1 = __ldg(base + (size_t)ia.y * VEC_PER_ROW);
    float4 v2 = __ldg(base + (size_t)ia.z * VEC_PER_ROW);
    float4 v3 = __ldg(base + (size_t)ia.w * VEC_PER_ROW);
    float4 v4 = __ldg(base + (size_t)ib.x * VEC_PER_ROW);
    float4 v5 = __ldg(base + (size_t)ib.y * VEC_PER_ROW);
    float4 v6 = __ldg(base + (size_t)ib.z * VEC_PER_ROW);
    float4 v7 = __ldg(base + (size_t)ib.w * VEC_PER_ROW);

    float4* dst = out + (size_t)row0 * VEC_PER_ROW + c;
    dst[0 * VEC_PER_ROW] = v0;
    dst[1 * VEC_PER_ROW] = v1;
    dst[2 * VEC_PER_ROW] = v2;
    dst[3 * VEC_PER_ROW] = v3;
    dst[4 * VEC_PER_ROW] = v4;
    dst[5 * VEC_PER_ROW] = v5;
    dst[6 * VEC_PER_ROW] = v6;
    dst[7 * VEC_PER_ROW] = v7;
}

extern "C" void kernel_launch(void* const* d_in, const int* in_sizes, int n_in,
                              void* d_out, int out_size) {
    const int*    x = (const int*)d_in[0];          // [16384] indices
    const float4* w = (const float4*)d_in[1];       // [50257*1024] fp32 as float4
    float4*       o = (float4*)d_out;

    int n_rows = in_sizes[0];                       // 16384
    int n_blocks = n_rows / ROWS_PER_BLOCK;         // 2048
    embedding_gather_kernel<<<n_blocks, 256>>>(x, w, o, n_rows);
}

// round 6
// speedup vs baseline: 1.0574x; 1.0574x over previous
#include <cuda_runtime.h>
#include <cuda_bf16.h>
#include <cstdint>

// Embedding gather: out[row, :] = w[x[row], :]
// x: [16384] int32, w: [50257, 1024] fp32, out: [16384, 1024] fp32
//
// Traffic-shaping strategy:
//   - w reads:  L2::evict_first  (200 MB stream, near-zero reuse -> don't pollute L2)
//   - out writes: L2::evict_last (64 MB fits in 126 MB L2 -> stays resident across
//     graph replays; steady-state DRAM write traffic ~0)
// 8 rows per block, 256 threads, MLP=8 front-batched LDG.128.

#define EMB_DIM 1024
#define VEC_PER_ROW (EMB_DIM / 4)   // 256 float4 per row
#define ROWS_PER_BLOCK 8

__device__ __forceinline__ float4 ldg_ef(const float4* p, uint64_t pol) {
    float4 v;
    asm volatile("ld.global.nc.L2::cache_hint.v4.f32 {%0,%1,%2,%3}, [%4], %5;"
                 : "=f"(v.x), "=f"(v.y), "=f"(v.z), "=f"(v.w)
                 : "l"(p), "l"(pol));
    return v;
}

__device__ __forceinline__ void stg_el(float4* p, float4 v, uint64_t pol) {
    asm volatile("st.global.L2::cache_hint.v4.f32 [%0], {%1,%2,%3,%4}, %5;"
                 :: "l"(p), "f"(v.x), "f"(v.y), "f"(v.z), "f"(v.w), "l"(pol)
                 : "memory");
}

__global__ void __launch_bounds__(256) embedding_gather_kernel(
    const int* __restrict__ x,
    const float4* __restrict__ w,
    float4* __restrict__ out,
    int n_rows)
{
    uint64_t pol_w, pol_o;
    asm("createpolicy.fractional.L2::evict_first.b64 %0, 1.0;" : "=l"(pol_w));
    asm("createpolicy.fractional.L2::evict_last.b64 %0, 1.0;"  : "=l"(pol_o));

    int row0 = blockIdx.x * ROWS_PER_BLOCK;
    int c = threadIdx.x;                       // column slot 0..255

    // Uniform index loads: 8 ints as two int4 (32B-aligned since row0%8==0)
    int4 ia = __ldg((const int4*)(x + row0));
    int4 ib = __ldg((const int4*)(x + row0 + 4));

    const float4* base = w + c;

    // Front-batched independent gathers: MLP = 8, evict-first in L2
    float4 v0 = ldg_ef(base + (size_t)ia.x * VEC_PER_ROW, pol_w);
    float4 v1 = ldg_ef(base + (size_t)ia.y * VEC_PER_ROW, pol_w);
    float4 v2 = ldg_ef(base + (size_t)ia.z * VEC_PER_ROW, pol_w);
    float4 v3 = ldg_ef(base + (size_t)ia.w * VEC_PER_ROW, pol_w);
    float4 v4 = ldg_ef(base + (size_t)ib.x * VEC_PER_ROW, pol_w);
    float4 v5 = ldg_ef(base + (size_t)ib.y * VEC_PER_ROW, pol_w);
    float4 v6 = ldg_ef(base + (size_t)ib.z * VEC_PER_ROW, pol_w);
    float4 v7 = ldg_ef(base + (size_t)ib.w * VEC_PER_ROW, pol_w);

    float4* dst = out + (size_t)row0 * VEC_PER_ROW + c;
    stg_el(dst + 0 * VEC_PER_ROW, v0, pol_o);
    stg_el(dst + 1 * VEC_PER_ROW, v1, pol_o);
    stg_el(dst + 2 * VEC_PER_ROW, v2, pol_o);
    stg_el(dst + 3 * VEC_PER_ROW, v3, pol_o);
    stg_el(dst + 4 * VEC_PER_ROW, v4, pol_o);
    stg_el(dst + 5 * VEC_PER_ROW, v5, pol_o);
    stg_el(dst + 6 * VEC_PER_ROW, v6, pol_o);
    stg_el(dst + 7 * VEC_PER_ROW, v7, pol_o);
}

extern "C" void kernel_launch(void* const* d_in, const int* in_sizes, int n_in,
                              void* d_out, int out_size) {
    const int*    x = (const int*)d_in[0];          // [16384] indices
    const float4* w = (const float4*)d_in[1];       // [50257*1024] fp32 as float4
    float4*       o = (float4*)d_out;

    int n_rows = in_sizes[0];                       // 16384
    int n_blocks = n_rows / ROWS_PER_BLOCK;         // 2048
    embedding_gather_kernel<<<n_blocks, 256>>>(x, w, o, n_rows);
}